// round 4
// baseline (speedup 1.0000x reference)
#include <cuda_runtime.h>
#include <cstdint>
#include <math.h>

#define NTOK 8192
#define DM   1024
#define HID  4096
#define NE   7

#define BM 128
#define BK 16
#define STAGES 4

// up stage layout (floats): A[128][20] ; Bg[16][136] ; Bu[16][136]
#define UP_SA 20
#define UP_SB 136
#define UP_A_OFF  0
#define UP_BG_OFF 10240
#define UP_BU_OFF 18944
#define UP_ST     27648

// down stage layout: A[128][20] ; B[16][264]
#define DN_SA 20
#define DN_SB 264
#define DN_A_OFF 0
#define DN_B_OFF 10240
#define DN_ST    27136

// ---------------- device scratch ----------------
__device__ int   g_cnt[NE];
__device__ int   g_off[NE + 1];
__device__ int   g_tok[NE * NTOK];
__device__ float g_wt [NE * NTOK];
__device__ int   g_dst[NE * NTOK];
__device__ float g_h[24576u * HID];
__device__ float g_y[NTOK * 3u * DM];
__device__ float g_cwg[NE * DM * HID];
__device__ float g_cwu[NE * DM * HID];
__device__ float g_cwd[NE * HID * DM];
__device__ float g_csg[DM * HID];
__device__ float g_csu[DM * HID];
__device__ float g_csd[HID * DM];
__device__ float g_cx [NTOK * DM];

// ---------------- helpers ----------------
__device__ __forceinline__ uint32_t smem_u32(const void* p) {
    uint32_t a;
    asm("{ .reg .u64 t; cvta.to.shared.u64 t, %1; cvt.u32.u64 %0, t; }" : "=r"(a) : "l"(p));
    return a;
}
__device__ __forceinline__ unsigned f2tf(float f) {
    unsigned u; asm("cvt.rna.tf32.f32 %0, %1;" : "=r"(u) : "f"(f)); return u;
}
__device__ __forceinline__ void cp16(uint32_t dst, const void* src) {
    asm volatile("cp.async.cg.shared.global [%0], [%1], 16;" :: "r"(dst), "l"(src));
}
#define CP_COMMIT() asm volatile("cp.async.commit_group;" ::: "memory")
#define CP_WAIT2()  asm volatile("cp.async.wait_group 2;" ::: "memory")

__device__ __forceinline__ void mma_tf32(float c[4], const unsigned a[4], const unsigned b[2]) {
    asm volatile(
        "mma.sync.aligned.m16n8k8.row.col.f32.tf32.tf32.f32 "
        "{%0,%1,%2,%3},{%4,%5,%6,%7},{%8,%9},{%0,%1,%2,%3};"
        : "+f"(c[0]), "+f"(c[1]), "+f"(c[2]), "+f"(c[3])
        : "r"(a[0]), "r"(a[1]), "r"(a[2]), "r"(a[3]), "r"(b[0]), "r"(b[1]));
}

// ---------------- tf32 pre-rounding ----------------
__global__ void __launch_bounds__(256) cvt_kernel(const float4* __restrict__ src, int which, int n4) {
    float4* dst;
    switch (which) {
        case 0: dst = (float4*)g_cwg; break;
        case 1: dst = (float4*)g_cwu; break;
        case 2: dst = (float4*)g_cwd; break;
        case 3: dst = (float4*)g_csg; break;
        case 4: dst = (float4*)g_csu; break;
        case 5: dst = (float4*)g_csd; break;
        default: dst = (float4*)g_cx; break;
    }
    int i = blockIdx.x * blockDim.x + threadIdx.x;
    if (i >= n4) return;
    float4 v = src[i];
    uint4 t; t.x = f2tf(v.x); t.y = f2tf(v.y); t.z = f2tf(v.z); t.w = f2tf(v.w);
    ((uint4*)dst)[i] = t;
}

__global__ void zero_kernel() { if (threadIdx.x < NE) g_cnt[threadIdx.x] = 0; }

__global__ void __launch_bounds__(256) router_kernel(const float* __restrict__ x,
                                                     const float* __restrict__ rw) {
    __shared__ float srw[NE * DM];
    for (int i = threadIdx.x; i < NE * DM; i += blockDim.x) srw[i] = rw[i];
    __syncthreads();
    int warp = (blockIdx.x * blockDim.x + threadIdx.x) >> 5;
    int lane = threadIdx.x & 31;
    if (warp >= NTOK) return;
    const float* xr = x + (size_t)warp * DM;
    float acc[NE];
#pragma unroll
    for (int e = 0; e < NE; e++) acc[e] = 0.f;
    for (int k = lane; k < DM; k += 32) {
        float xv = xr[k];
#pragma unroll
        for (int e = 0; e < NE; e++) acc[e] += xv * srw[e * DM + k];
    }
#pragma unroll
    for (int e = 0; e < NE; e++) {
#pragma unroll
        for (int o = 16; o > 0; o >>= 1) acc[e] += __shfl_xor_sync(0xffffffffu, acc[e], o);
    }
    if (lane == 0) {
        int i1 = 0; float v1 = acc[0];
#pragma unroll
        for (int e = 1; e < NE; e++) if (acc[e] > v1) { v1 = acc[e]; i1 = e; }
        int i2 = -1; float v2 = -1e30f;
#pragma unroll
        for (int e = 0; e < NE; e++) if (e != i1 && acc[e] > v2) { v2 = acc[e]; i2 = e; }
        float w1 = 1.f / (1.f + expf(v2 - v1));
        float w2 = 1.f - w1;
        int p1 = atomicAdd(&g_cnt[i1], 1);
        g_tok[i1 * NTOK + p1] = warp; g_wt[i1 * NTOK + p1] = w1; g_dst[i1 * NTOK + p1] = warp * 3 + 0;
        int p2 = atomicAdd(&g_cnt[i2], 1);
        g_tok[i2 * NTOK + p2] = warp; g_wt[i2 * NTOK + p2] = w2; g_dst[i2 * NTOK + p2] = warp * 3 + 1;
    }
}

__global__ void scan_kernel() {
    if (threadIdx.x == 0) {
        int s = 0;
        for (int e = 0; e < NE; e++) { g_off[e] = s; s += g_cnt[e]; }
        g_off[NE] = s;
    }
}

// ============================================================================
// up kernel: CTA 128x128 (dual-matrix), warp tile 64x32 per matrix, occ 1.
// ============================================================================
__global__ void __launch_bounds__(256, 1) up_kernel() {
    int grp = blockIdx.z;
    int cnt, hbase;
    const float *pg, *pu;
    if (grp < NE) {
        cnt = g_cnt[grp]; hbase = g_off[grp];
        pg = g_cwg + (size_t)grp * DM * HID;
        pu = g_cwu + (size_t)grp * DM * HID;
    } else { cnt = NTOK; hbase = 16384; pg = g_csg; pu = g_csu; }
    int mt0 = blockIdx.x * BM;
    if (mt0 >= cnt) return;
    int n0 = blockIdx.y * 128;

    extern __shared__ __align__(16) char smem[];
    uint32_t sb = smem_u32(smem);
    int tid = threadIdx.x;

    // A: one row per thread-pair: row = tid>>1, k-chunk (tid&1)*8 (+0,+4)
    int arow = tid >> 1;
    int akc = (tid & 1) * 8;
    int lrA = mt0 + arow; if (lrA >= cnt) lrA = mt0;
    int tokA = (grp < NE) ? g_tok[grp * NTOK + lrA] : lrA;
    const float* asrc = g_cx + (size_t)tokA * DM + akc;
    uint32_t adst = (uint32_t)(arow * UP_SA * 4 + akc * 4);
    // B: krow tid>>4 (0..15), col chunk (tid&15)*8 (+0,+4), both matrices
    int bkr = tid >> 4, bnc = (tid & 15) * 8;
    const float* bgsrc = pg + (size_t)bkr * HID + n0 + bnc;
    const float* busrc = pu + (size_t)bkr * HID + n0 + bnc;
    uint32_t bdst = (uint32_t)(bkr * UP_SB * 4 + bnc * 4);

    const int NKT = DM / BK;   // 64
    auto issue = [&](int kt) {
        uint32_t st = sb + (uint32_t)(kt & 3) * UP_ST;
        size_t k0 = (size_t)kt * BK;
        const float* a = asrc + k0;
        cp16(st + UP_A_OFF + adst, a);
        cp16(st + UP_A_OFF + adst + 16, a + 4);
        const float* bg = bgsrc + k0 * HID;
        const float* bu = busrc + k0 * HID;
        cp16(st + UP_BG_OFF + bdst, bg);
        cp16(st + UP_BG_OFF + bdst + 16, bg + 4);
        cp16(st + UP_BU_OFF + bdst, bu);
        cp16(st + UP_BU_OFF + bdst + 16, bu + 4);
    };

    issue(0); CP_COMMIT();
    issue(1); CP_COMMIT();
    issue(2); CP_COMMIT();

    int warp = tid >> 5, lane = tid & 31;
    int wm = (warp & 1) * 64;
    int wn = (warp >> 1) * 32;
    int gid = lane >> 2, tig = lane & 3;

    float accG[4][4][4], accU[4][4][4];
#pragma unroll
    for (int a = 0; a < 4; a++)
#pragma unroll
        for (int b = 0; b < 4; b++)
#pragma unroll
            for (int c = 0; c < 4; c++) { accG[a][b][c] = 0.f; accU[a][b][c] = 0.f; }

    for (int kt = 0; kt < NKT; kt++) {
        CP_WAIT2();
        __syncthreads();
        if (kt + 3 < NKT) issue(kt + 3);
        CP_COMMIT();
        const unsigned* sA  = (const unsigned*)(smem + (size_t)(kt & 3) * UP_ST + UP_A_OFF);
        const unsigned* sBg = (const unsigned*)(smem + (size_t)(kt & 3) * UP_ST + UP_BG_OFF);
        const unsigned* sBu = (const unsigned*)(smem + (size_t)(kt & 3) * UP_ST + UP_BU_OFF);
#pragma unroll
        for (int ks = 0; ks < 2; ks++) {
            int k0 = ks * 8;
            unsigned af[4][4];
#pragma unroll
            for (int mt = 0; mt < 4; mt++) {
                int rb = wm + mt * 16 + gid;
                af[mt][0] = sA[rb * UP_SA + k0 + tig];
                af[mt][1] = sA[(rb + 8) * UP_SA + k0 + tig];
                af[mt][2] = sA[rb * UP_SA + k0 + 4 + tig];
                af[mt][3] = sA[(rb + 8) * UP_SA + k0 + 4 + tig];
            }
            unsigned bg[4][2], bu[4][2];
#pragma unroll
            for (int nt = 0; nt < 4; nt++) {
                int cb = wn + nt * 8 + gid;
                bg[nt][0] = sBg[(k0 + tig) * UP_SB + cb];
                bg[nt][1] = sBg[(k0 + 4 + tig) * UP_SB + cb];
                bu[nt][0] = sBu[(k0 + tig) * UP_SB + cb];
                bu[nt][1] = sBu[(k0 + 4 + tig) * UP_SB + cb];
            }
#pragma unroll
            for (int nt = 0; nt < 4; nt++)
#pragma unroll
                for (int mt = 0; mt < 4; mt++) {
                    mma_tf32(accG[mt][nt], af[mt], bg[nt]);
                    mma_tf32(accU[mt][nt], af[mt], bu[nt]);
                }
        }
    }

    // epilogue: h = silu(g)*u (tf32-rounded for down GEMM)
#pragma unroll
    for (int mt = 0; mt < 4; mt++) {
#pragma unroll
        for (int i = 0; i < 4; i++) {
            int row = wm + mt * 16 + gid + ((i & 2) ? 8 : 0);
            int lr = mt0 + row;
            if (lr >= cnt) continue;
            size_t base = (size_t)(hbase + lr) * HID + n0 + wn;
#pragma unroll
            for (int nt = 0; nt < 4; nt++) {
                float g = accG[mt][nt][i], u = accU[mt][nt][i];
                float h = g * u / (1.f + __expf(-g));
                g_h[base + nt * 8 + tig * 2 + (i & 1)] = __uint_as_float(f2tf(h));
            }
        }
    }
}

// ============================================================================
// down kernel: CTA 128x256, warp tile 64x64, occ 1.
// ============================================================================
__global__ void __launch_bounds__(256, 1) down_kernel() {
    int grp = blockIdx.z;
    int cnt, hbase;
    const float* pd;
    if (grp < NE) { cnt = g_cnt[grp]; hbase = g_off[grp]; pd = g_cwd + (size_t)grp * HID * DM; }
    else          { cnt = NTOK;       hbase = 16384;      pd = g_csd; }
    int mt0 = blockIdx.x * BM;
    if (mt0 >= cnt) return;
    int n0 = blockIdx.y * 256;

    extern __shared__ __align__(16) char smem[];
    uint32_t sb = smem_u32(smem);
    int tid = threadIdx.x;

    int arow = tid >> 1;
    int akc = (tid & 1) * 8;
    int lrA = mt0 + arow; if (lrA >= cnt) lrA = mt0;
    const float* asrc = g_h + (size_t)(hbase + lrA) * HID + akc;
    uint32_t adst = (uint32_t)(arow * DN_SA * 4 + akc * 4);
    int bkr = tid >> 4, bnc = (tid & 15) * 16;
    const float* bsrc = pd + (size_t)bkr * DM + n0 + bnc;
    uint32_t bdst = (uint32_t)(bkr * DN_SB * 4 + bnc * 4);

    const int NKT = HID / BK;  // 256
    auto issue = [&](int kt) {
        uint32_t st = sb + (uint32_t)(kt & 3) * DN_ST;
        size_t k0 = (size_t)kt * BK;
        const float* a = asrc + k0;
        cp16(st + DN_A_OFF + adst, a);
        cp16(st + DN_A_OFF + adst + 16, a + 4);
        const float* b = bsrc + k0 * DM;
        cp16(st + DN_B_OFF + bdst,      b);
        cp16(st + DN_B_OFF + bdst + 16, b + 4);
        cp16(st + DN_B_OFF + bdst + 32, b + 8);
        cp16(st + DN_B_OFF + bdst + 48, b + 12);
    };

    issue(0); CP_COMMIT();
    issue(1); CP_COMMIT();
    issue(2); CP_COMMIT();

    int warp = tid >> 5, lane = tid & 31;
    int wm = (warp & 1) * 64;
    int wn = (warp >> 1) * 64;
    int gid = lane >> 2, tig = lane & 3;

    float acc[4][8][4];
#pragma unroll
    for (int a = 0; a < 4; a++)
#pragma unroll
        for (int b = 0; b < 8; b++)
#pragma unroll
            for (int c = 0; c < 4; c++) acc[a][b][c] = 0.f;

    for (int kt = 0; kt < NKT; kt++) {
        CP_WAIT2();
        __syncthreads();
        if (kt + 3 < NKT) issue(kt + 3);
        CP_COMMIT();
        const unsigned* sA = (const unsigned*)(smem + (size_t)(kt & 3) * DN_ST + DN_A_OFF);
        const unsigned* sB = (const unsigned*)(smem + (size_t)(kt & 3) * DN_ST + DN_B_OFF);
#pragma unroll
        for (int ks = 0; ks < 2; ks++) {
            int k0 = ks * 8;
            unsigned af[4][4];
#pragma unroll
            for (int mt = 0; mt < 4; mt++) {
                int rb = wm + mt * 16 + gid;
                af[mt][0] = sA[rb * DN_SA + k0 + tig];
                af[mt][1] = sA[(rb + 8) * DN_SA + k0 + tig];
                af[mt][2] = sA[rb * DN_SA + k0 + 4 + tig];
                af[mt][3] = sA[(rb + 8) * DN_SA + k0 + 4 + tig];
            }
#pragma unroll
            for (int nt = 0; nt < 8; nt++) {
                int cb = wn + nt * 8 + gid;
                unsigned bf[2];
                bf[0] = sB[(k0 + tig) * DN_SB + cb];
                bf[1] = sB[(k0 + 4 + tig) * DN_SB + cb];
#pragma unroll
                for (int mt = 0; mt < 4; mt++) mma_tf32(acc[mt][nt], af[mt], bf);
            }
        }
    }

    // epilogue: y[dst] = wt * acc (8 distinct rows per thread)
    int dsts[8]; float wts[8]; int valid[8];
#pragma unroll
    for (int j = 0; j < 8; j++) {
        int row = wm + (j >> 1) * 16 + gid + ((j & 1) ? 8 : 0);
        int lr = mt0 + row;
        valid[j] = (lr < cnt);
        int lc = valid[j] ? lr : mt0;
        if (grp < NE) { int q = grp * NTOK + lc; dsts[j] = g_dst[q]; wts[j] = g_wt[q]; }
        else          { dsts[j] = lc * 3 + 2;    wts[j] = 1.f; }
    }
#pragma unroll
    for (int mt = 0; mt < 4; mt++)
#pragma unroll
        for (int i = 0; i < 4; i++) {
            int j = mt * 2 + ((i & 2) ? 1 : 0);
            if (!valid[j]) continue;
            size_t base = (size_t)dsts[j] * DM + n0 + wn;
#pragma unroll
            for (int nt = 0; nt < 8; nt++)
                g_y[base + nt * 8 + tig * 2 + (i & 1)] = wts[j] * acc[mt][nt][i];
        }
}

// ---------------- combine ----------------
__global__ void combine_kernel(float* __restrict__ out) {
    int i = blockIdx.x * blockDim.x + threadIdx.x;
    if (i >= NTOK * DM) return;
    int n = i / DM, c = i % DM;
    size_t b = (size_t)n * 3 * DM + c;
    out[i] = g_y[b] + g_y[b + DM] + g_y[b + 2 * DM];
}

// ---------------- launch ----------------
extern "C" void kernel_launch(void* const* d_in, const int* in_sizes, int n_in,
                              void* d_out, int out_size) {
    const float* x   = (const float*)d_in[0];
    const float* rw  = (const float*)d_in[1];
    const float* wg  = (const float*)d_in[2];
    const float* wu  = (const float*)d_in[3];
    const float* wd  = (const float*)d_in[4];
    const float* swg = (const float*)d_in[5];
    const float* swu = (const float*)d_in[6];
    const float* swd = (const float*)d_in[7];
    float* out = (float*)d_out;

    const int UP_SMEM = STAGES * UP_ST;   // 110592
    const int DN_SMEM = STAGES * DN_ST;   // 108544
    cudaFuncSetAttribute(up_kernel,   cudaFuncAttributeMaxDynamicSharedMemorySize, UP_SMEM);
    cudaFuncSetAttribute(down_kernel, cudaFuncAttributeMaxDynamicSharedMemorySize, DN_SMEM);

    const int RW = NE * DM * HID / 4;
    const int SW = DM * HID / 4;
    const int XW = NTOK * DM / 4;
    cvt_kernel<<<(RW + 255) / 256, 256>>>((const float4*)wg,  0, RW);
    cvt_kernel<<<(RW + 255) / 256, 256>>>((const float4*)wu,  1, RW);
    cvt_kernel<<<(RW + 255) / 256, 256>>>((const float4*)wd,  2, RW);
    cvt_kernel<<<(SW + 255) / 256, 256>>>((const float4*)swg, 3, SW);
    cvt_kernel<<<(SW + 255) / 256, 256>>>((const float4*)swu, 4, SW);
    cvt_kernel<<<(SW + 255) / 256, 256>>>((const float4*)swd, 5, SW);
    cvt_kernel<<<(XW + 255) / 256, 256>>>((const float4*)x,   6, XW);

    zero_kernel<<<1, 32>>>();
    router_kernel<<<NTOK / 8, 256>>>(x, rw);
    scan_kernel<<<1, 32>>>();

    dim3 gu(NTOK / BM, HID / 128, 8);   // (64, 32, 8)
    up_kernel<<<gu, 256, UP_SMEM>>>();

    dim3 gd(NTOK / BM, DM / 256, 8);    // (64, 4, 8)
    down_kernel<<<gd, 256, DN_SMEM>>>();

    combine_kernel<<<(NTOK * DM) / 256, 256>>>(out);
}

// round 6
// speedup vs baseline: 1.1070x; 1.1070x over previous
#include <cuda_runtime.h>
#include <cstdint>
#include <math.h>

#define NTOK 8192
#define DM   1024
#define HID  4096
#define NE   7

#define BM 128
#define BK 16
#define STAGES 4

// up stage (floats): A[128][20] @0 ; Bg[2][8][64] @10240B ; Bu @14336B ; 18432B/stage
#define UP_SA 20
#define UP_A_OFF  0
#define UP_BG_OFF 10240
#define UP_BU_OFF 14336
#define UP_ST     18432
// down stage: A[128][20] @0 ; B[2][16][64] @10240B ; 18432B/stage
#define DN_SA 20
#define DN_B_OFF 10240
#define DN_ST    18432

// ---------------- device scratch ----------------
__device__ int   g_cnt[NE];
__device__ int   g_off[NE + 1];
__device__ int   g_tok[NE * NTOK];
__device__ float g_wt [NE * NTOK];
__device__ int   g_dst[NE * NTOK];
__device__ float g_h[24576u * HID];        // hidden acts, A-perm layout
__device__ float g_y[NTOK * 3u * DM];
// fragment-tiled tf32 weights
__device__ float g_cwg[NE * DM * HID];
__device__ float g_cwu[NE * DM * HID];
__device__ float g_cwd[NE * HID * DM];
__device__ float g_csg[DM * HID];
__device__ float g_csu[DM * HID];
__device__ float g_csd[HID * DM];
__device__ float g_cx [NTOK * DM];         // x, A-perm layout

// ---------------- helpers ----------------
__device__ __forceinline__ uint32_t smem_u32(const void* p) {
    uint32_t a;
    asm("{ .reg .u64 t; cvta.to.shared.u64 t, %1; cvt.u32.u64 %0, t; }" : "=r"(a) : "l"(p));
    return a;
}
__device__ __forceinline__ unsigned f2tf(float f) {
    unsigned u; asm("cvt.rna.tf32.f32 %0, %1;" : "=r"(u) : "f"(f)); return u;
}
__device__ __forceinline__ void cp16(uint32_t dst, const void* src) {
    asm volatile("cp.async.cg.shared.global [%0], [%1], 16;" :: "r"(dst), "l"(src));
}
#define CP_COMMIT() asm volatile("cp.async.commit_group;" ::: "memory")
#define CP_WAIT2()  asm volatile("cp.async.wait_group 2;" ::: "memory")

__device__ __forceinline__ void mma_tf32(float c[4], const unsigned a[4], const unsigned b[2]) {
    asm volatile(
        "mma.sync.aligned.m16n8k8.row.col.f32.tf32.tf32.f32 "
        "{%0,%1,%2,%3},{%4,%5,%6,%7},{%8,%9},{%0,%1,%2,%3};"
        : "+f"(c[0]), "+f"(c[1]), "+f"(c[2]), "+f"(c[3])
        : "r"(a[0]), "r"(a[1]), "r"(a[2]), "r"(a[3]), "r"(b[0]), "r"(b[1]));
}

// ---------------- cvt: x -> tf32 + A-perm [c0,c4,c1,c5,c2,c6,c3,c7] ----------------
__global__ void __launch_bounds__(256) cvt_x_kernel(const float4* __restrict__ src, int n8) {
    float4* dst = (float4*)g_cx;
    int i = blockIdx.x * blockDim.x + threadIdx.x;
    if (i >= n8) return;
    float4 v0 = src[i * 2], v1 = src[i * 2 + 1];
    uint4 o0, o1;
    o0.x = f2tf(v0.x); o0.y = f2tf(v1.x); o0.z = f2tf(v0.y); o0.w = f2tf(v1.y);
    o1.x = f2tf(v0.z); o1.y = f2tf(v1.z); o1.z = f2tf(v0.w); o1.w = f2tf(v1.w);
    ((uint4*)dst)[i * 2] = o0; ((uint4*)dst)[i * 2 + 1] = o1;
}

// ---------------- cvt: weights -> tf32 + 8x8 fragment tiles ----------------
// src K x N row-major; dst blocks [k/8][n/8][64]: pos(lane,reg) holds
// B[k = (lane&3)+reg*4][n = lane>>2] at tile offset lane*2+reg.
__global__ void __launch_bounds__(256) cvt_w_kernel(const float* __restrict__ src, int which,
                                                    int K, int N) {
    float* dstb;
    switch (which) {
        case 0: dstb = g_cwg; break;
        case 1: dstb = g_cwu; break;
        case 2: dstb = g_cwd; break;
        case 3: dstb = g_csg; break;
        case 4: dstb = g_csu; break;
        default: dstb = g_csd; break;
    }
    __shared__ float st[16 * 132];
    size_t moff = (size_t)blockIdx.z * K * N;
    const float* s0 = src + moff;
    float* dst = dstb + moff;
    int k0 = blockIdx.x * 16, n0 = blockIdx.y * 128;
    int tid = threadIdx.x;
    int rr = tid >> 4, rc = (tid & 15) * 8;
    const float* s = s0 + (size_t)(k0 + rr) * N + n0 + rc;
    float4 a = *(const float4*)s, b = *(const float4*)(s + 4);
    float* d = &st[rr * 132 + rc];
    d[0]=a.x; d[1]=a.y; d[2]=a.z; d[3]=a.w; d[4]=b.x; d[5]=b.y; d[6]=b.z; d[7]=b.w;
    __syncthreads();
    int tile = tid >> 3;             // 0..31 : kk = tile>>4, nn = tile&15
    int kk = tile >> 4, nn = tile & 15;
    int t8 = tid & 7;
    uint4 o[2];
    unsigned* ov = (unsigned*)o;
#pragma unroll
    for (int j = 0; j < 8; j++) {
        int f = t8 * 8 + j;
        int lane = f >> 1, reg = f & 1;
        int kin = kk * 8 + (lane & 3) + reg * 4;
        int nin = nn * 8 + (lane >> 2);
        ov[j] = f2tf(st[kin * 132 + nin]);
    }
    size_t ob = ((size_t)(k0 / 8 + kk) * (N / 8) + (n0 / 8 + nn)) * 64 + t8 * 8;
    *(uint4*)(dst + ob) = o[0];
    *(uint4*)(dst + ob + 4) = o[1];
}

__global__ void zero_kernel() { if (threadIdx.x < NE) g_cnt[threadIdx.x] = 0; }

__global__ void __launch_bounds__(256) router_kernel(const float* __restrict__ x,
                                                     const float* __restrict__ rw) {
    __shared__ float srw[NE * DM];
    for (int i = threadIdx.x; i < NE * DM; i += blockDim.x) srw[i] = rw[i];
    __syncthreads();
    int warp = (blockIdx.x * blockDim.x + threadIdx.x) >> 5;
    int lane = threadIdx.x & 31;
    if (warp >= NTOK) return;
    const float* xr = x + (size_t)warp * DM;
    float acc[NE];
#pragma unroll
    for (int e = 0; e < NE; e++) acc[e] = 0.f;
    for (int k = lane; k < DM; k += 32) {
        float xv = xr[k];
#pragma unroll
        for (int e = 0; e < NE; e++) acc[e] += xv * srw[e * DM + k];
    }
#pragma unroll
    for (int e = 0; e < NE; e++) {
#pragma unroll
        for (int o = 16; o > 0; o >>= 1) acc[e] += __shfl_xor_sync(0xffffffffu, acc[e], o);
    }
    if (lane == 0) {
        int i1 = 0; float v1 = acc[0];
#pragma unroll
        for (int e = 1; e < NE; e++) if (acc[e] > v1) { v1 = acc[e]; i1 = e; }
        int i2 = -1; float v2 = -1e30f;
#pragma unroll
        for (int e = 0; e < NE; e++) if (e != i1 && acc[e] > v2) { v2 = acc[e]; i2 = e; }
        float w1 = 1.f / (1.f + expf(v2 - v1));
        float w2 = 1.f - w1;
        int p1 = atomicAdd(&g_cnt[i1], 1);
        g_tok[i1 * NTOK + p1] = warp; g_wt[i1 * NTOK + p1] = w1; g_dst[i1 * NTOK + p1] = warp * 3 + 0;
        int p2 = atomicAdd(&g_cnt[i2], 1);
        g_tok[i2 * NTOK + p2] = warp; g_wt[i2 * NTOK + p2] = w2; g_dst[i2 * NTOK + p2] = warp * 3 + 1;
    }
}

__global__ void scan_kernel() {
    if (threadIdx.x == 0) {
        int s = 0;
        for (int e = 0; e < NE; e++) { g_off[e] = s; s += g_cnt[e]; }
        g_off[NE] = s;
    }
}

// ============================================================================
// up kernel: CTA 128x64 dual-matrix, warps 4m x 2n (32x32/warp), occ 2.
// ============================================================================
__global__ void __launch_bounds__(256, 2) up_kernel() {
    int grp = blockIdx.z;
    int cnt, hbase;
    const float *pg, *pu;
    if (grp < NE) {
        cnt = g_cnt[grp]; hbase = g_off[grp];
        pg = g_cwg + (size_t)grp * DM * HID;
        pu = g_cwu + (size_t)grp * DM * HID;
    } else { cnt = NTOK; hbase = 16384; pg = g_csg; pu = g_csu; }
    int mt0 = blockIdx.x * BM;
    if (mt0 >= cnt) return;
    int n0 = blockIdx.y * 64;

    extern __shared__ __align__(16) char smem[];
    uint32_t sb = smem_u32(smem);
    int tid = threadIdx.x;

    // A: rows tid>>2, +64; 16B at float (tid&3)*4
    int arow0 = tid >> 2, arow1 = arow0 + 64;
    int akc = (tid & 3) * 4;
    int lr0 = mt0 + arow0; if (lr0 >= cnt) lr0 = mt0;
    int lr1 = mt0 + arow1; if (lr1 >= cnt) lr1 = mt0;
    int tok0 = (grp < NE) ? g_tok[grp * NTOK + lr0] : lr0;
    int tok1 = (grp < NE) ? g_tok[grp * NTOK + lr1] : lr1;
    const float* asrc0 = g_cx + (size_t)tok0 * DM + akc;
    const float* asrc1 = g_cx + (size_t)tok1 * DM + akc;
    uint32_t adst0 = (uint32_t)(arow0 * UP_SA * 4 + akc * 4);
    uint32_t adst1 = (uint32_t)(arow1 * UP_SA * 4 + akc * 4);
    // B tiled: per stage 4KB/matrix; thread copies chunk tid (ks = tid>>7)
    const float* bgsrc = pg + (size_t)n0 * 8 + (tid & 127) * 4 + (size_t)(tid >> 7) * HID * 8;
    const float* busrc = pu + (size_t)n0 * 8 + (tid & 127) * 4 + (size_t)(tid >> 7) * HID * 8;
    uint32_t bdst = (uint32_t)(tid * 16);

    const int NKT = DM / BK;   // 64
    auto issue = [&](int kt) {
        uint32_t st = sb + (uint32_t)(kt & 3) * UP_ST;
        size_t ka = (size_t)kt * BK;
        cp16(st + UP_A_OFF + adst0, asrc0 + ka);
        cp16(st + UP_A_OFF + adst1, asrc1 + ka);
        size_t kb = (size_t)kt * HID * 16;
        cp16(st + UP_BG_OFF + bdst, bgsrc + kb);
        cp16(st + UP_BU_OFF + bdst, busrc + kb);
    };

    issue(0); CP_COMMIT();
    issue(1); CP_COMMIT();
    issue(2); CP_COMMIT();

    int warp = tid >> 5, lane = tid & 31;
    int wm = (warp & 3) * 32;
    int wng = warp >> 2;            // n-group 0/1
    int gid = lane >> 2, tig = lane & 3;

    float accG[2][4][4], accU[2][4][4];
#pragma unroll
    for (int a = 0; a < 2; a++)
#pragma unroll
        for (int b = 0; b < 4; b++)
#pragma unroll
            for (int c = 0; c < 4; c++) { accG[a][b][c] = 0.f; accU[a][b][c] = 0.f; }

    for (int kt = 0; kt < NKT; kt++) {
        CP_WAIT2();
        __syncthreads();
        if (kt + 3 < NKT) issue(kt + 3);
        CP_COMMIT();
        const unsigned* sA  = (const unsigned*)(smem + (size_t)(kt & 3) * UP_ST + UP_A_OFF);
        const unsigned* sBg = (const unsigned*)(smem + (size_t)(kt & 3) * UP_ST + UP_BG_OFF);
        const unsigned* sBu = (const unsigned*)(smem + (size_t)(kt & 3) * UP_ST + UP_BU_OFF);
#pragma unroll
        for (int ks = 0; ks < 2; ks++) {
            int k0 = ks * 8;
            unsigned af[2][4];
#pragma unroll
            for (int mt = 0; mt < 2; mt++) {
                int rb = wm + mt * 16 + gid;
                uint2 a0 = *(const uint2*)&sA[rb * UP_SA + k0 + tig * 2];
                uint2 a1 = *(const uint2*)&sA[(rb + 8) * UP_SA + k0 + tig * 2];
                af[mt][0] = a0.x; af[mt][2] = a0.y;
                af[mt][1] = a1.x; af[mt][3] = a1.y;
            }
#pragma unroll
            for (int nt = 0; nt < 4; nt++) {
                int idx = (ks * 8 + wng * 4 + nt) * 64 + lane * 2;
                uint2 gv = *(const uint2*)&sBg[idx];
                uint2 uv = *(const uint2*)&sBu[idx];
                unsigned bg[2] = { gv.x, gv.y }, bu[2] = { uv.x, uv.y };
#pragma unroll
                for (int mt = 0; mt < 2; mt++) {
                    mma_tf32(accG[mt][nt], af[mt], bg);
                    mma_tf32(accU[mt][nt], af[mt], bu);
                }
            }
        }
    }

    // epilogue: h = silu(g)*u, tf32-rounded, A-perm layout for down GEMM
    int wn = wng * 32;
#pragma unroll
    for (int mt = 0; mt < 2; mt++) {
#pragma unroll
        for (int i = 0; i < 4; i++) {
            int row = wm + mt * 16 + gid + ((i & 2) ? 8 : 0);
            int lr = mt0 + row;
            if (lr >= cnt) continue;
            size_t base = (size_t)(hbase + lr) * HID + n0 + wn;
            int c8 = tig * 2 + (i & 1);
            int p = (c8 & 3) * 2 + (c8 >> 2);
#pragma unroll
            for (int nt = 0; nt < 4; nt++) {
                float g = accG[mt][nt][i], u = accU[mt][nt][i];
                float h = g * u / (1.f + __expf(-g));
                g_h[base + nt * 8 + p] = __uint_as_float(f2tf(h));
            }
        }
    }
}

// ============================================================================
// down kernel: CTA 128x128, warps 4m x 2n (32x64/warp), occ 2.
// ============================================================================
__global__ void __launch_bounds__(256, 2) down_kernel() {
    int grp = blockIdx.z;
    int cnt, hbase;
    const float* pd;
    if (grp < NE) { cnt = g_cnt[grp]; hbase = g_off[grp]; pd = g_cwd + (size_t)grp * HID * DM; }
    else          { cnt = NTOK;       hbase = 16384;      pd = g_csd; }
    int mt0 = blockIdx.x * BM;
    if (mt0 >= cnt) return;
    int n0 = blockIdx.y * 128;

    extern __shared__ __align__(16) char smem[];
    uint32_t sb = smem_u32(smem);
    int tid = threadIdx.x;

    int arow0 = tid >> 2, arow1 = arow0 + 64;
    int akc = (tid & 3) * 4;
    int lr0 = mt0 + arow0; if (lr0 >= cnt) lr0 = mt0;
    int lr1 = mt0 + arow1; if (lr1 >= cnt) lr1 = mt0;
    const float* asrc0 = g_h + (size_t)(hbase + lr0) * HID + akc;
    const float* asrc1 = g_h + (size_t)(hbase + lr1) * HID + akc;
    uint32_t adst0 = (uint32_t)(arow0 * DN_SA * 4 + akc * 4);
    uint32_t adst1 = (uint32_t)(arow1 * DN_SA * 4 + akc * 4);
    const float* bsrc = pd + (size_t)n0 * 8 + tid * 4;
    uint32_t bdst = (uint32_t)(tid * 16);

    const int NKT = HID / BK;  // 256
    auto issue = [&](int kt) {
        uint32_t st = sb + (uint32_t)(kt & 3) * DN_ST;
        size_t ka = (size_t)kt * BK;
        cp16(st + adst0, asrc0 + ka);
        cp16(st + adst1, asrc1 + ka);
        size_t kb = (size_t)kt * DM * 16;
        cp16(st + DN_B_OFF + bdst,        bsrc + kb);
        cp16(st + DN_B_OFF + 4096 + bdst, bsrc + kb + DM * 8);
    };

    issue(0); CP_COMMIT();
    issue(1); CP_COMMIT();
    issue(2); CP_COMMIT();

    int warp = tid >> 5, lane = tid & 31;
    int wm = (warp & 3) * 32;
    int wng = warp >> 2;            // n-group 0/1 (64 cols each)
    int gid = lane >> 2, tig = lane & 3;

    float acc[2][8][4];
#pragma unroll
    for (int a = 0; a < 2; a++)
#pragma unroll
        for (int b = 0; b < 8; b++)
#pragma unroll
            for (int c = 0; c < 4; c++) acc[a][b][c] = 0.f;

    for (int kt = 0; kt < NKT; kt++) {
        CP_WAIT2();
        __syncthreads();
        if (kt + 3 < NKT) issue(kt + 3);
        CP_COMMIT();
        const unsigned* sA = (const unsigned*)(smem + (size_t)(kt & 3) * DN_ST);
        const unsigned* sB = (const unsigned*)(smem + (size_t)(kt & 3) * DN_ST + DN_B_OFF);
#pragma unroll
        for (int ks = 0; ks < 2; ks++) {
            int k0 = ks * 8;
            unsigned af[2][4];
#pragma unroll
            for (int mt = 0; mt < 2; mt++) {
                int rb = wm + mt * 16 + gid;
                uint2 a0 = *(const uint2*)&sA[rb * DN_SA + k0 + tig * 2];
                uint2 a1 = *(const uint2*)&sA[(rb + 8) * DN_SA + k0 + tig * 2];
                af[mt][0] = a0.x; af[mt][2] = a0.y;
                af[mt][1] = a1.x; af[mt][3] = a1.y;
            }
#pragma unroll
            for (int nt = 0; nt < 8; nt++) {
                int idx = (ks * 16 + wng * 8 + nt) * 64 + lane * 2;
                uint2 bv = *(const uint2*)&sB[idx];
                unsigned bf[2] = { bv.x, bv.y };
#pragma unroll
                for (int mt = 0; mt < 2; mt++) mma_tf32(acc[mt][nt], af[mt], bf);
            }
        }
    }

    // epilogue: y[dst] = wt * acc (standard layout)
    int wn = wng * 64;
    int dsts[4]; float wts[4]; int valid[4];
    int rws[4] = { wm + gid, wm + gid + 8, wm + 16 + gid, wm + 24 + gid };
#pragma unroll
    for (int j = 0; j < 4; j++) {
        int lr = mt0 + rws[j];
        valid[j] = (lr < cnt);
        int lc = valid[j] ? lr : mt0;
        if (grp < NE) { int q = grp * NTOK + lc; dsts[j] = g_dst[q]; wts[j] = g_wt[q]; }
        else          { dsts[j] = lc * 3 + 2;    wts[j] = 1.f; }
    }
#pragma unroll
    for (int mt = 0; mt < 2; mt++)
#pragma unroll
        for (int i = 0; i < 4; i++) {
            int j = mt * 2 + ((i & 2) ? 1 : 0);
            if (!valid[j]) continue;
            size_t base = (size_t)dsts[j] * DM + n0 + wn;
#pragma unroll
            for (int nt = 0; nt < 8; nt++)
                g_y[base + nt * 8 + tig * 2 + (i & 1)] = wts[j] * acc[mt][nt][i];
        }
}

// ---------------- combine ----------------
__global__ void combine_kernel(float* __restrict__ out) {
    int i = blockIdx.x * blockDim.x + threadIdx.x;
    if (i >= NTOK * DM) return;
    int n = i / DM, c = i % DM;
    size_t b = (size_t)n * 3 * DM + c;
    out[i] = g_y[b] + g_y[b + DM] + g_y[b + 2 * DM];
}

// ---------------- launch ----------------
extern "C" void kernel_launch(void* const* d_in, const int* in_sizes, int n_in,
                              void* d_out, int out_size) {
    const float* x   = (const float*)d_in[0];
    const float* rw  = (const float*)d_in[1];
    const float* wg  = (const float*)d_in[2];
    const float* wu  = (const float*)d_in[3];
    const float* wd  = (const float*)d_in[4];
    const float* swg = (const float*)d_in[5];
    const float* swu = (const float*)d_in[6];
    const float* swd = (const float*)d_in[7];
    float* out = (float*)d_out;

    const int UP_SMEM = STAGES * UP_ST;   // 73728
    const int DN_SMEM = STAGES * DN_ST;   // 73728
    cudaFuncSetAttribute(up_kernel,   cudaFuncAttributeMaxDynamicSharedMemorySize, UP_SMEM);
    cudaFuncSetAttribute(down_kernel, cudaFuncAttributeMaxDynamicSharedMemorySize, DN_SMEM);

    // weight cvt -> fragment-tiled tf32 (dst resolved device-side)
    dim3 gw(DM / 16, HID / 128, NE);      // (64, 32, 7)
    cvt_w_kernel<<<gw, 256>>>(wg, 0, DM, HID);
    cvt_w_kernel<<<gw, 256>>>(wu, 1, DM, HID);
    dim3 gwd(HID / 16, DM / 128, NE);     // (256, 8, 7)
    cvt_w_kernel<<<gwd, 256>>>(wd, 2, HID, DM);
    dim3 gs(DM / 16, HID / 128, 1);
    cvt_w_kernel<<<gs, 256>>>(swg, 3, DM, HID);
    cvt_w_kernel<<<gs, 256>>>(swu, 4, DM, HID);
    dim3 gsd(HID / 16, DM / 128, 1);
    cvt_w_kernel<<<gsd, 256>>>(swd, 5, HID, DM);
    // x cvt -> A-perm tf32 (dst resolved device-side)
    const int X8 = NTOK * DM / 8;
    cvt_x_kernel<<<(X8 + 255) / 256, 256>>>((const float4*)x, X8);

    zero_kernel<<<1, 32>>>();
    router_kernel<<<NTOK / 8, 256>>>(x, rw);
    scan_kernel<<<1, 32>>>();

    dim3 gu(NTOK / BM, HID / 64, 8);    // (64, 64, 8)
    up_kernel<<<gu, 256, UP_SMEM>>>();

    dim3 gd(NTOK / BM, DM / 128, 8);    // (64, 8, 8)
    down_kernel<<<gd, 256, DN_SMEM>>>();

    combine_kernel<<<(NTOK * DM) / 256, 256>>>(out);
}

// round 8
// speedup vs baseline: 1.9171x; 1.7317x over previous
#include <cuda_runtime.h>
#include <cuda_fp16.h>
#include <cstdint>
#include <math.h>

#define NTOK 8192
#define DM   1024
#define HID  4096
#define NE   7

#define BM 128
#define BKH 32              // K per tile, in halves (64 bytes)
#define STAGES 4

// up stage: A[128 rows x 80B] @0 ; Bg[64 x 80B] @10240 ; Bu @15360 ; 20480B/stage
#define SAW 20              // words (4B) per smem row (40 halves, 16 data + 4 pad)
#define UP_BG_OFF 10240
#define UP_BU_OFF 15360
#define UP_ST     20480
// down stage: A[128 x 80B] @0 ; B[128 x 80B] @10240 ; 20480B/stage
#define DN_B_OFF 10240
#define DN_ST    20480

// ---------------- device scratch ----------------
__device__ int    g_cnt[NE];
__device__ int    g_off[NE + 1];
__device__ int    g_tok[NE * NTOK];
__device__ float  g_wt [NE * NTOK];
__device__ int    g_dst[NE * NTOK];
__device__ __half g_h[24576u * HID];       // hidden acts fp16 [slot][k]
__device__ float  g_y[NTOK * 3u * DM];
// fp16 transposed weights [N][K] + fp16 x [tok][k]
__device__ __half g_cwg[NE * DM * HID];
__device__ __half g_cwu[NE * DM * HID];
__device__ __half g_cwd[NE * HID * DM];
__device__ __half g_csg[DM * HID];
__device__ __half g_csu[DM * HID];
__device__ __half g_csd[HID * DM];
__device__ __half g_cx [NTOK * DM];

// ---------------- helpers ----------------
__device__ __forceinline__ uint32_t smem_u32(const void* p) {
    uint32_t a;
    asm("{ .reg .u64 t; cvta.to.shared.u64 t, %1; cvt.u32.u64 %0, t; }" : "=r"(a) : "l"(p));
    return a;
}
__device__ __forceinline__ void cp16(uint32_t dst, const void* src) {
    asm volatile("cp.async.cg.shared.global [%0], [%1], 16;" :: "r"(dst), "l"(src));
}
#define CP_COMMIT() asm volatile("cp.async.commit_group;" ::: "memory")
#define CP_WAIT2()  asm volatile("cp.async.wait_group 2;" ::: "memory")

__device__ __forceinline__ void mma_f16(float c[4], const unsigned a[4], const unsigned b[2]) {
    asm volatile(
        "mma.sync.aligned.m16n8k16.row.col.f32.f16.f16.f32 "
        "{%0,%1,%2,%3},{%4,%5,%6,%7},{%8,%9},{%0,%1,%2,%3};"
        : "+f"(c[0]), "+f"(c[1]), "+f"(c[2]), "+f"(c[3])
        : "r"(a[0]), "r"(a[1]), "r"(a[2]), "r"(a[3]), "r"(b[0]), "r"(b[1]));
}

// ---------------- cvt: x -> fp16 [tok][k] ----------------
__global__ void __launch_bounds__(256) cvt_x_kernel(const float4* __restrict__ src, int n8) {
    int i = blockIdx.x * blockDim.x + threadIdx.x;
    if (i >= n8) return;
    float4 v0 = src[i * 2], v1 = src[i * 2 + 1];
    __half2 h[4];
    h[0] = __floats2half2_rn(v0.x, v0.y);
    h[1] = __floats2half2_rn(v0.z, v0.w);
    h[2] = __floats2half2_rn(v1.x, v1.y);
    h[3] = __floats2half2_rn(v1.z, v1.w);
    ((uint4*)g_cx)[i] = *(uint4*)h;
}

// ---------------- cvt: weight [K][N] f32 -> [N][K] fp16 (transpose) ----------------
__global__ void __launch_bounds__(256) cvt_wT_kernel(const float* __restrict__ src, int which,
                                                     int K, int N) {
    __half* dstb;
    switch (which) {
        case 0: dstb = g_cwg; break;
        case 1: dstb = g_cwu; break;
        case 2: dstb = g_cwd; break;
        case 3: dstb = g_csg; break;
        case 4: dstb = g_csu; break;
        default: dstb = g_csd; break;
    }
    __shared__ float st[64][65];
    size_t mo = (size_t)blockIdx.z * K * N;
    const float* s = src + mo;
    __half* d = dstb + mo;
    int k0 = blockIdx.x * 64, n0 = blockIdx.y * 64;
    int tid = threadIdx.x;
    int rk = tid >> 2, cn = (tid & 3) * 16;
    const float4* p = (const float4*)(s + (size_t)(k0 + rk) * N + n0 + cn);
#pragma unroll
    for (int j = 0; j < 4; j++) {
        float4 v = p[j];
        st[rk][cn + j * 4 + 0] = v.x; st[rk][cn + j * 4 + 1] = v.y;
        st[rk][cn + j * 4 + 2] = v.z; st[rk][cn + j * 4 + 3] = v.w;
    }
    __syncthreads();
    int rn = tid >> 2, ck = (tid & 3) * 16;
    __half2 o[8];
#pragma unroll
    for (int j = 0; j < 8; j++)
        o[j] = __floats2half2_rn(st[ck + j * 2][rn], st[ck + j * 2 + 1][rn]);
    uint4* q = (uint4*)(d + (size_t)(n0 + rn) * K + k0 + ck);
    q[0] = ((uint4*)o)[0];
    q[1] = ((uint4*)o)[1];
}

__global__ void zero_kernel() { if (threadIdx.x < NE) g_cnt[threadIdx.x] = 0; }

__global__ void __launch_bounds__(256) router_kernel(const float* __restrict__ x,
                                                     const float* __restrict__ rw) {
    __shared__ float srw[NE * DM];
    for (int i = threadIdx.x; i < NE * DM; i += blockDim.x) srw[i] = rw[i];
    __syncthreads();
    int warp = (blockIdx.x * blockDim.x + threadIdx.x) >> 5;
    int lane = threadIdx.x & 31;
    if (warp >= NTOK) return;
    const float* xr = x + (size_t)warp * DM;
    float acc[NE];
#pragma unroll
    for (int e = 0; e < NE; e++) acc[e] = 0.f;
    for (int k = lane; k < DM; k += 32) {
        float xv = xr[k];
#pragma unroll
        for (int e = 0; e < NE; e++) acc[e] += xv * srw[e * DM + k];
    }
#pragma unroll
    for (int e = 0; e < NE; e++) {
#pragma unroll
        for (int o = 16; o > 0; o >>= 1) acc[e] += __shfl_xor_sync(0xffffffffu, acc[e], o);
    }
    if (lane == 0) {
        int i1 = 0; float v1 = acc[0];
#pragma unroll
        for (int e = 1; e < NE; e++) if (acc[e] > v1) { v1 = acc[e]; i1 = e; }
        int i2 = -1; float v2 = -1e30f;
#pragma unroll
        for (int e = 0; e < NE; e++) if (e != i1 && acc[e] > v2) { v2 = acc[e]; i2 = e; }
        float w1 = 1.f / (1.f + expf(v2 - v1));
        float w2 = 1.f - w1;
        int p1 = atomicAdd(&g_cnt[i1], 1);
        g_tok[i1 * NTOK + p1] = warp; g_wt[i1 * NTOK + p1] = w1; g_dst[i1 * NTOK + p1] = warp * 3 + 0;
        int p2 = atomicAdd(&g_cnt[i2], 1);
        g_tok[i2 * NTOK + p2] = warp; g_wt[i2 * NTOK + p2] = w2; g_dst[i2 * NTOK + p2] = warp * 3 + 1;
    }
}

__global__ void scan_kernel() {
    if (threadIdx.x == 0) {
        int s = 0;
        for (int e = 0; e < NE; e++) { g_off[e] = s; s += g_cnt[e]; }
        g_off[NE] = s;
    }
}

// ============================================================================
// up kernel: CTA 128m x 64n dual-matrix fp16, warps 4m x 2n (32x32/warp), occ 2.
// ============================================================================
__global__ void __launch_bounds__(256, 2) up_kernel() {
    int grp = blockIdx.z;
    int cnt, hbase;
    const __half *pg, *pu;
    if (grp < NE) {
        cnt = g_cnt[grp]; hbase = g_off[grp];
        pg = g_cwg + (size_t)grp * DM * HID;
        pu = g_cwu + (size_t)grp * DM * HID;
    } else { cnt = NTOK; hbase = 16384; pg = g_csg; pu = g_csu; }
    int mt0 = blockIdx.x * BM;
    if (mt0 >= cnt) return;
    int n0 = blockIdx.y * 64;

    extern __shared__ __align__(16) char smem[];
    uint32_t sb = smem_u32(smem);
    int tid = threadIdx.x;

    // A: row = tid>>1 (one token row), 32B half (tid&1)
    int arow = tid >> 1, ac = tid & 1;
    int lrA = mt0 + arow; if (lrA >= cnt) lrA = mt0;
    int tokA = (grp < NE) ? g_tok[grp * NTOK + lrA] : lrA;
    const __half* asrc = g_cx + (size_t)tokA * DM + ac * 16;
    uint32_t adst = (uint32_t)(arow * 80 + ac * 32);
    // B: row = tid>>2 (n), 16B chunk (tid&3)
    int brow = tid >> 2, bc = tid & 3;
    const __half* bgsrc = pg + (size_t)(n0 + brow) * DM + bc * 8;
    const __half* busrc = pu + (size_t)(n0 + brow) * DM + bc * 8;
    uint32_t bdst = (uint32_t)(brow * 80 + bc * 16);

    const int NKT = DM / BKH;   // 32
    auto issue = [&](int kt) {
        uint32_t st = sb + (uint32_t)(kt & 3) * UP_ST;
        size_t kh = (size_t)kt * BKH;
        cp16(st + adst,      asrc + kh);
        cp16(st + adst + 16, asrc + kh + 8);
        cp16(st + UP_BG_OFF + bdst, bgsrc + kh);
        cp16(st + UP_BU_OFF + bdst, busrc + kh);
    };

    issue(0); CP_COMMIT();
    issue(1); CP_COMMIT();
    issue(2); CP_COMMIT();

    int warp = tid >> 5, lane = tid & 31;
    int wm = (warp & 3) * 32;
    int wng = warp >> 2;
    int gid = lane >> 2, tig = lane & 3;

    float accG[2][4][4], accU[2][4][4];
#pragma unroll
    for (int a = 0; a < 2; a++)
#pragma unroll
        for (int b = 0; b < 4; b++)
#pragma unroll
            for (int c = 0; c < 4; c++) { accG[a][b][c] = 0.f; accU[a][b][c] = 0.f; }

    for (int kt = 0; kt < NKT; kt++) {
        CP_WAIT2();
        __syncthreads();
        if (kt + 3 < NKT) issue(kt + 3);
        CP_COMMIT();
        const unsigned* sA  = (const unsigned*)(smem + (size_t)(kt & 3) * UP_ST);
        const unsigned* sBg = (const unsigned*)(smem + (size_t)(kt & 3) * UP_ST + UP_BG_OFF);
        const unsigned* sBu = (const unsigned*)(smem + (size_t)(kt & 3) * UP_ST + UP_BU_OFF);
#pragma unroll
        for (int ks = 0; ks < 2; ks++) {
            int k0 = ks * 8;
            unsigned af[2][4];
#pragma unroll
            for (int mt = 0; mt < 2; mt++) {
                int rb = wm + mt * 16 + gid;
                af[mt][0] = sA[rb * SAW + k0 + tig];
                af[mt][1] = sA[(rb + 8) * SAW + k0 + tig];
                af[mt][2] = sA[rb * SAW + k0 + 4 + tig];
                af[mt][3] = sA[(rb + 8) * SAW + k0 + 4 + tig];
            }
#pragma unroll
            for (int nt = 0; nt < 4; nt++) {
                int nb = (wng * 32 + nt * 8 + gid) * SAW + k0;
                unsigned bg[2], bu[2];
                bg[0] = sBg[nb + tig]; bg[1] = sBg[nb + 4 + tig];
                bu[0] = sBu[nb + tig]; bu[1] = sBu[nb + 4 + tig];
#pragma unroll
                for (int mt = 0; mt < 2; mt++) {
                    mma_f16(accG[mt][nt], af[mt], bg);
                    mma_f16(accU[mt][nt], af[mt], bu);
                }
            }
        }
    }

    // epilogue: h = silu(g)*u -> fp16 half2 stores
    int wn = wng * 32;
#pragma unroll
    for (int mt = 0; mt < 2; mt++) {
#pragma unroll
        for (int rr = 0; rr < 2; rr++) {
            int row = wm + mt * 16 + gid + rr * 8;
            int lr = mt0 + row;
            if (lr >= cnt) continue;
            __half* hp = g_h + (size_t)(hbase + lr) * HID + n0 + wn + tig * 2;
#pragma unroll
            for (int nt = 0; nt < 4; nt++) {
                float g0 = accG[mt][nt][rr * 2], u0 = accU[mt][nt][rr * 2];
                float g1 = accG[mt][nt][rr * 2 + 1], u1 = accU[mt][nt][rr * 2 + 1];
                float h0 = g0 * u0 / (1.f + __expf(-g0));
                float h1 = g1 * u1 / (1.f + __expf(-g1));
                *(__half2*)(hp + nt * 8) = __floats2half2_rn(h0, h1);
            }
        }
    }
}

// ============================================================================
// down kernel: CTA 128m x 128n fp16, warps 4m x 2n (32x64/warp), occ 2.
// ============================================================================
__global__ void __launch_bounds__(256, 2) down_kernel() {
    int grp = blockIdx.z;
    int cnt, hbase;
    const __half* pd;
    if (grp < NE) { cnt = g_cnt[grp]; hbase = g_off[grp]; pd = g_cwd + (size_t)grp * HID * DM; }
    else          { cnt = NTOK;       hbase = 16384;      pd = g_csd; }
    int mt0 = blockIdx.x * BM;
    if (mt0 >= cnt) return;
    int n0 = blockIdx.y * 128;

    extern __shared__ __align__(16) char smem[];
    uint32_t sb = smem_u32(smem);
    int tid = threadIdx.x;

    int arow = tid >> 1, ac = tid & 1;
    int lrA = mt0 + arow; if (lrA >= cnt) lrA = mt0;
    const __half* asrc = g_h + (size_t)(hbase + lrA) * HID + ac * 16;
    uint32_t adst = (uint32_t)(arow * 80 + ac * 32);
    const __half* bsrc = pd + (size_t)(n0 + arow) * HID + ac * 16;
    uint32_t bdst = (uint32_t)(arow * 80 + ac * 32);

    const int NKT = HID / BKH;  // 128
    auto issue = [&](int kt) {
        uint32_t st = sb + (uint32_t)(kt & 3) * DN_ST;
        size_t kh = (size_t)kt * BKH;
        cp16(st + adst,      asrc + kh);
        cp16(st + adst + 16, asrc + kh + 8);
        cp16(st + DN_B_OFF + bdst,      bsrc + kh);
        cp16(st + DN_B_OFF + bdst + 16, bsrc + kh + 8);
    };

    issue(0); CP_COMMIT();
    issue(1); CP_COMMIT();
    issue(2); CP_COMMIT();

    int warp = tid >> 5, lane = tid & 31;
    int wm = (warp & 3) * 32;
    int wng = warp >> 2;
    int gid = lane >> 2, tig = lane & 3;

    float acc[2][8][4];
#pragma unroll
    for (int a = 0; a < 2; a++)
#pragma unroll
        for (int b = 0; b < 8; b++)
#pragma unroll
            for (int c = 0; c < 4; c++) acc[a][b][c] = 0.f;

    for (int kt = 0; kt < NKT; kt++) {
        CP_WAIT2();
        __syncthreads();
        if (kt + 3 < NKT) issue(kt + 3);
        CP_COMMIT();
        const unsigned* sA = (const unsigned*)(smem + (size_t)(kt & 3) * DN_ST);
        const unsigned* sB = (const unsigned*)(smem + (size_t)(kt & 3) * DN_ST + DN_B_OFF);
#pragma unroll
        for (int ks = 0; ks < 2; ks++) {
            int k0 = ks * 8;
            unsigned af[2][4];
#pragma unroll
            for (int mt = 0; mt < 2; mt++) {
                int rb = wm + mt * 16 + gid;
                af[mt][0] = sA[rb * SAW + k0 + tig];
                af[mt][1] = sA[(rb + 8) * SAW + k0 + tig];
                af[mt][2] = sA[rb * SAW + k0 + 4 + tig];
                af[mt][3] = sA[(rb + 8) * SAW + k0 + 4 + tig];
            }
#pragma unroll
            for (int nt = 0; nt < 8; nt++) {
                int nb = (wng * 64 + nt * 8 + gid) * SAW + k0;
                unsigned bf[2];
                bf[0] = sB[nb + tig]; bf[1] = sB[nb + 4 + tig];
#pragma unroll
                for (int mt = 0; mt < 2; mt++) mma_f16(acc[mt][nt], af[mt], bf);
            }
        }
    }

    // epilogue: y[dst] = wt * acc (float2 stores)
    int wn = wng * 64;
#pragma unroll
    for (int mt = 0; mt < 2; mt++) {
#pragma unroll
        for (int rr = 0; rr < 2; rr++) {
            int row = wm + mt * 16 + gid + rr * 8;
            int lr = mt0 + row;
            if (lr >= cnt) continue;
            int dst; float wt;
            if (grp < NE) { int q = grp * NTOK + lr; dst = g_dst[q]; wt = g_wt[q]; }
            else          { dst = lr * 3 + 2;        wt = 1.f; }
            float* yp = g_y + (size_t)dst * DM + n0 + wn + tig * 2;
#pragma unroll
            for (int nt = 0; nt < 8; nt++) {
                float2 o;
                o.x = wt * acc[mt][nt][rr * 2];
                o.y = wt * acc[mt][nt][rr * 2 + 1];
                *(float2*)(yp + nt * 8) = o;
            }
        }
    }
}

// ---------------- combine ----------------
__global__ void combine_kernel(float* __restrict__ out) {
    int i = blockIdx.x * blockDim.x + threadIdx.x;
    if (i >= NTOK * DM) return;
    int n = i / DM, c = i % DM;
    size_t b = (size_t)n * 3 * DM + c;
    out[i] = g_y[b] + g_y[b + DM] + g_y[b + 2 * DM];
}

// ---------------- launch ----------------
extern "C" void kernel_launch(void* const* d_in, const int* in_sizes, int n_in,
                              void* d_out, int out_size) {
    const float* x   = (const float*)d_in[0];
    const float* rw  = (const float*)d_in[1];
    const float* wg  = (const float*)d_in[2];
    const float* wu  = (const float*)d_in[3];
    const float* wd  = (const float*)d_in[4];
    const float* swg = (const float*)d_in[5];
    const float* swu = (const float*)d_in[6];
    const float* swd = (const float*)d_in[7];
    float* out = (float*)d_out;

    const int UP_SMEM = STAGES * UP_ST;   // 81920
    const int DN_SMEM = STAGES * DN_ST;   // 81920
    cudaFuncSetAttribute(up_kernel,   cudaFuncAttributeMaxDynamicSharedMemorySize, UP_SMEM);
    cudaFuncSetAttribute(down_kernel, cudaFuncAttributeMaxDynamicSharedMemorySize, DN_SMEM);

    // weight cvt -> transposed fp16
    dim3 gw(DM / 64, HID / 64, NE);      // (16, 64, 7)
    cvt_wT_kernel<<<gw, 256>>>(wg, 0, DM, HID);
    cvt_wT_kernel<<<gw, 256>>>(wu, 1, DM, HID);
    dim3 gwd(HID / 64, DM / 64, NE);     // (64, 16, 7)
    cvt_wT_kernel<<<gwd, 256>>>(wd, 2, HID, DM);
    dim3 gs(DM / 64, HID / 64, 1);
    cvt_wT_kernel<<<gs, 256>>>(swg, 3, DM, HID);
    cvt_wT_kernel<<<gs, 256>>>(swu, 4, DM, HID);
    dim3 gsd(HID / 64, DM / 64, 1);
    cvt_wT_kernel<<<gsd, 256>>>(swd, 5, HID, DM);
    const int X8 = NTOK * DM / 8;
    cvt_x_kernel<<<(X8 + 255) / 256, 256>>>((const float4*)x, X8);

    zero_kernel<<<1, 32>>>();
    router_kernel<<<NTOK / 8, 256>>>(x, rw);
    scan_kernel<<<1, 32>>>();

    dim3 gu(NTOK / BM, HID / 64, 8);    // (64, 64, 8)
    up_kernel<<<gu, 256, UP_SMEM>>>();

    dim3 gd(NTOK / BM, DM / 128, 8);    // (64, 8, 8)
    down_kernel<<<gd, 256, DN_SMEM>>>();

    combine_kernel<<<(NTOK * DM) / 256, 256>>>(out);
}

// round 9
// speedup vs baseline: 2.3730x; 1.2378x over previous
#include <cuda_runtime.h>
#include <cuda_fp16.h>
#include <cstdint>
#include <math.h>

#define NTOK 8192
#define DM   1024
#define HID  4096
#define NE   7

#define BM 128
#define BKH 64              // K per tile in halves (128 bytes)
#define STAGES 3
#define RSB 144             // bytes per smem row (128 data + 16 pad)

// up stage: A[128 x 144B] @0 ; Bg[64 x 144B] @18432 ; Bu @27648 ; 36864B/stage
#define UP_BG_OFF 18432
#define UP_BU_OFF 27648
#define UP_ST     36864
// down stage: A[128 x 144B] @0 ; B[128 x 144B] @18432 ; 36864B/stage
#define DN_B_OFF 18432
#define DN_ST    36864

// ---------------- device scratch ----------------
__device__ int    g_cnt[NE];
__device__ int    g_off[NE + 1];
__device__ int    g_tok[NE * NTOK];
__device__ float  g_wt [NE * NTOK];
__device__ int    g_dst[NE * NTOK];
__device__ __half g_h[24576u * HID];
__device__ float  g_y[NTOK * 3u * DM];
__device__ __half g_cwg[NE * DM * HID];
__device__ __half g_cwu[NE * DM * HID];
__device__ __half g_cwd[NE * HID * DM];
__device__ __half g_csg[DM * HID];
__device__ __half g_csu[DM * HID];
__device__ __half g_csd[HID * DM];
__device__ __half g_cx [NTOK * DM];

// ---------------- helpers ----------------
__device__ __forceinline__ uint32_t smem_u32(const void* p) {
    uint32_t a;
    asm("{ .reg .u64 t; cvta.to.shared.u64 t, %1; cvt.u32.u64 %0, t; }" : "=r"(a) : "l"(p));
    return a;
}
__device__ __forceinline__ void cp16(uint32_t dst, const void* src) {
    asm volatile("cp.async.cg.shared.global [%0], [%1], 16;" :: "r"(dst), "l"(src));
}
#define CP_COMMIT() asm volatile("cp.async.commit_group;" ::: "memory")
#define CP_WAIT1()  asm volatile("cp.async.wait_group 1;" ::: "memory")

__device__ __forceinline__ void ldsm4(unsigned r[4], uint32_t addr) {
    asm volatile("ldmatrix.sync.aligned.m8n8.x4.shared.b16 {%0,%1,%2,%3}, [%4];"
        : "=r"(r[0]), "=r"(r[1]), "=r"(r[2]), "=r"(r[3]) : "r"(addr));
}
__device__ __forceinline__ void mma_f16(float c[4], const unsigned a[4], const unsigned b[2]) {
    asm volatile(
        "mma.sync.aligned.m16n8k16.row.col.f32.f16.f16.f32 "
        "{%0,%1,%2,%3},{%4,%5,%6,%7},{%8,%9},{%0,%1,%2,%3};"
        : "+f"(c[0]), "+f"(c[1]), "+f"(c[2]), "+f"(c[3])
        : "r"(a[0]), "r"(a[1]), "r"(a[2]), "r"(a[3]), "r"(b[0]), "r"(b[1]));
}

// ---------------- cvt: x -> fp16 ----------------
__global__ void __launch_bounds__(256) cvt_x_kernel(const float4* __restrict__ src, int n8) {
    int i = blockIdx.x * blockDim.x + threadIdx.x;
    if (i >= n8) return;
    float4 v0 = src[i * 2], v1 = src[i * 2 + 1];
    __half2 h[4];
    h[0] = __floats2half2_rn(v0.x, v0.y);
    h[1] = __floats2half2_rn(v0.z, v0.w);
    h[2] = __floats2half2_rn(v1.x, v1.y);
    h[3] = __floats2half2_rn(v1.z, v1.w);
    ((uint4*)g_cx)[i] = *(uint4*)h;
}

// ---------------- cvt: weight [K][N] f32 -> [N][K] fp16 (transpose) ----------------
__global__ void __launch_bounds__(256) cvt_wT_kernel(const float* __restrict__ src, int which,
                                                     int K, int N) {
    __half* dstb;
    switch (which) {
        case 0: dstb = g_cwg; break;
        case 1: dstb = g_cwu; break;
        case 2: dstb = g_cwd; break;
        case 3: dstb = g_csg; break;
        case 4: dstb = g_csu; break;
        default: dstb = g_csd; break;
    }
    __shared__ float st[64][65];
    size_t mo = (size_t)blockIdx.z * K * N;
    const float* s = src + mo;
    __half* d = dstb + mo;
    int k0 = blockIdx.x * 64, n0 = blockIdx.y * 64;
    int tid = threadIdx.x;
    int rk = tid >> 2, cn = (tid & 3) * 16;
    const float4* p = (const float4*)(s + (size_t)(k0 + rk) * N + n0 + cn);
#pragma unroll
    for (int j = 0; j < 4; j++) {
        float4 v = p[j];
        st[rk][cn + j * 4 + 0] = v.x; st[rk][cn + j * 4 + 1] = v.y;
        st[rk][cn + j * 4 + 2] = v.z; st[rk][cn + j * 4 + 3] = v.w;
    }
    __syncthreads();
    int rn = tid >> 2, ck = (tid & 3) * 16;
    __half2 o[8];
#pragma unroll
    for (int j = 0; j < 8; j++)
        o[j] = __floats2half2_rn(st[ck + j * 2][rn], st[ck + j * 2 + 1][rn]);
    uint4* q = (uint4*)(d + (size_t)(n0 + rn) * K + k0 + ck);
    q[0] = ((uint4*)o)[0];
    q[1] = ((uint4*)o)[1];
}

__global__ void zero_kernel() { if (threadIdx.x < NE) g_cnt[threadIdx.x] = 0; }

__global__ void __launch_bounds__(256) router_kernel(const float* __restrict__ x,
                                                     const float* __restrict__ rw) {
    __shared__ float srw[NE * DM];
    for (int i = threadIdx.x; i < NE * DM; i += blockDim.x) srw[i] = rw[i];
    __syncthreads();
    int warp = (blockIdx.x * blockDim.x + threadIdx.x) >> 5;
    int lane = threadIdx.x & 31;
    if (warp >= NTOK) return;
    const float* xr = x + (size_t)warp * DM;
    float acc[NE];
#pragma unroll
    for (int e = 0; e < NE; e++) acc[e] = 0.f;
    for (int k = lane; k < DM; k += 32) {
        float xv = xr[k];
#pragma unroll
        for (int e = 0; e < NE; e++) acc[e] += xv * srw[e * DM + k];
    }
#pragma unroll
    for (int e = 0; e < NE; e++) {
#pragma unroll
        for (int o = 16; o > 0; o >>= 1) acc[e] += __shfl_xor_sync(0xffffffffu, acc[e], o);
    }
    if (lane == 0) {
        int i1 = 0; float v1 = acc[0];
#pragma unroll
        for (int e = 1; e < NE; e++) if (acc[e] > v1) { v1 = acc[e]; i1 = e; }
        int i2 = -1; float v2 = -1e30f;
#pragma unroll
        for (int e = 0; e < NE; e++) if (e != i1 && acc[e] > v2) { v2 = acc[e]; i2 = e; }
        float w1 = 1.f / (1.f + expf(v2 - v1));
        float w2 = 1.f - w1;
        int p1 = atomicAdd(&g_cnt[i1], 1);
        g_tok[i1 * NTOK + p1] = warp; g_wt[i1 * NTOK + p1] = w1; g_dst[i1 * NTOK + p1] = warp * 3 + 0;
        int p2 = atomicAdd(&g_cnt[i2], 1);
        g_tok[i2 * NTOK + p2] = warp; g_wt[i2 * NTOK + p2] = w2; g_dst[i2 * NTOK + p2] = warp * 3 + 1;
    }
}

__global__ void scan_kernel() {
    if (threadIdx.x == 0) {
        int s = 0;
        for (int e = 0; e < NE; e++) { g_off[e] = s; s += g_cnt[e]; }
        g_off[NE] = s;
    }
}

// ============================================================================
// up kernel: CTA 128m x 64n dual-matrix fp16, BKH=64, LDSM, 3-stage, occ 2.
// ============================================================================
__global__ void __launch_bounds__(256, 2) up_kernel() {
    int grp = blockIdx.z;
    int cnt, hbase;
    const __half *pg, *pu;
    if (grp < NE) {
        cnt = g_cnt[grp]; hbase = g_off[grp];
        pg = g_cwg + (size_t)grp * DM * HID;
        pu = g_cwu + (size_t)grp * DM * HID;
    } else { cnt = NTOK; hbase = 16384; pg = g_csg; pu = g_csu; }
    int mt0 = blockIdx.x * BM;
    if (mt0 >= cnt) return;
    int n0 = blockIdx.y * 64;

    extern __shared__ __align__(16) char smem[];
    uint32_t sb = smem_u32(smem);
    int tid = threadIdx.x;

    // producers: A 4 chunks (rows tid>>3 + i*32), B 2 chunks per matrix
    int arow = tid >> 3;
    int acol = (tid & 7) * 8;        // halves
    const __half* asrc[4];
#pragma unroll
    for (int i = 0; i < 4; i++) {
        int lr = mt0 + arow + i * 32; if (lr >= cnt) lr = mt0;
        int tok = (grp < NE) ? g_tok[grp * NTOK + lr] : lr;
        asrc[i] = g_cx + (size_t)tok * DM + acol;
    }
    uint32_t adst = (uint32_t)(arow * RSB + (tid & 7) * 16);
    const __half* bg0 = pg + (size_t)(n0 + arow) * DM + acol;
    const __half* bg1 = pg + (size_t)(n0 + 32 + arow) * DM + acol;
    const __half* bu0 = pu + (size_t)(n0 + arow) * DM + acol;
    const __half* bu1 = pu + (size_t)(n0 + 32 + arow) * DM + acol;
    uint32_t bdst = adst;

    const int NKT = DM / BKH;   // 16
    auto issue = [&](int s, int kt) {
        uint32_t st = sb + (uint32_t)s * UP_ST;
        size_t kh = (size_t)kt * BKH;
#pragma unroll
        for (int i = 0; i < 4; i++) cp16(st + adst + i * 32 * RSB, asrc[i] + kh);
        cp16(st + UP_BG_OFF + bdst,            bg0 + kh);
        cp16(st + UP_BG_OFF + bdst + 32 * RSB, bg1 + kh);
        cp16(st + UP_BU_OFF + bdst,            bu0 + kh);
        cp16(st + UP_BU_OFF + bdst + 32 * RSB, bu1 + kh);
    };

    issue(0, 0); CP_COMMIT();
    issue(1, 1); CP_COMMIT();

    int warp = tid >> 5, lane = tid & 31;
    int wm = (warp & 3) * 32;
    int wng = warp >> 2;
    int gid = lane >> 2, tig = lane & 3;
    int lg = lane >> 3, l8 = lane & 7;
    // ldsm base offsets (within stage): row += (lg&1)*8, koff = (lg>>1)*16
    uint32_t a_ls = (uint32_t)((wm + (lg & 1) * 8 + l8) * RSB + (lg >> 1) * 16);
    uint32_t b_ls = (uint32_t)((wng * 32 + (lg & 1) * 8 + l8) * RSB + (lg >> 1) * 16);

    float accG[2][4][4], accU[2][4][4];
#pragma unroll
    for (int a = 0; a < 2; a++)
#pragma unroll
        for (int b = 0; b < 4; b++)
#pragma unroll
            for (int c = 0; c < 4; c++) { accG[a][b][c] = 0.f; accU[a][b][c] = 0.f; }

    int slot = 0;
    for (int kt = 0; kt < NKT; kt++) {
        CP_WAIT1();
        __syncthreads();
        if (kt + 2 < NKT) {
            int s2 = slot + 2; if (s2 >= STAGES) s2 -= STAGES;
            issue(s2, kt + 2); CP_COMMIT();
        }
        uint32_t stg = sb + (uint32_t)slot * UP_ST;
#pragma unroll
        for (int ks = 0; ks < 4; ks++) {
            uint32_t ko = ks * 32;
            unsigned af[2][4];
            ldsm4(af[0], stg + a_ls + ko);
            ldsm4(af[1], stg + a_ls + 16 * RSB + ko);
#pragma unroll
            for (int j = 0; j < 2; j++) {
                unsigned gb[4], ub[4];
                ldsm4(gb, stg + UP_BG_OFF + b_ls + j * 16 * RSB + ko);
                ldsm4(ub, stg + UP_BU_OFF + b_ls + j * 16 * RSB + ko);
                unsigned bge[2] = { gb[0], gb[2] }, bgo[2] = { gb[1], gb[3] };
                unsigned bue[2] = { ub[0], ub[2] }, buo[2] = { ub[1], ub[3] };
#pragma unroll
                for (int mt = 0; mt < 2; mt++) {
                    mma_f16(accG[mt][j * 2],     af[mt], bge);
                    mma_f16(accG[mt][j * 2 + 1], af[mt], bgo);
                    mma_f16(accU[mt][j * 2],     af[mt], bue);
                    mma_f16(accU[mt][j * 2 + 1], af[mt], buo);
                }
            }
        }
        if (++slot == STAGES) slot = 0;
    }

    // epilogue: h = silu(g)*u -> fp16
    int wn = wng * 32;
#pragma unroll
    for (int mt = 0; mt < 2; mt++) {
#pragma unroll
        for (int rr = 0; rr < 2; rr++) {
            int row = wm + mt * 16 + gid + rr * 8;
            int lr = mt0 + row;
            if (lr >= cnt) continue;
            __half* hp = g_h + (size_t)(hbase + lr) * HID + n0 + wn + tig * 2;
#pragma unroll
            for (int nt = 0; nt < 4; nt++) {
                float g0 = accG[mt][nt][rr * 2], u0 = accU[mt][nt][rr * 2];
                float g1 = accG[mt][nt][rr * 2 + 1], u1 = accU[mt][nt][rr * 2 + 1];
                float h0 = g0 * u0 / (1.f + __expf(-g0));
                float h1 = g1 * u1 / (1.f + __expf(-g1));
                *(__half2*)(hp + nt * 8) = __floats2half2_rn(h0, h1);
            }
        }
    }
}

// ============================================================================
// down kernel: CTA 128m x 128n fp16, BKH=64, LDSM, 3-stage, occ 2.
// ============================================================================
__global__ void __launch_bounds__(256, 2) down_kernel() {
    int grp = blockIdx.z;
    int cnt, hbase;
    const __half* pd;
    if (grp < NE) { cnt = g_cnt[grp]; hbase = g_off[grp]; pd = g_cwd + (size_t)grp * HID * DM; }
    else          { cnt = NTOK;       hbase = 16384;      pd = g_csd; }
    int mt0 = blockIdx.x * BM;
    if (mt0 >= cnt) return;
    int n0 = blockIdx.y * 128;

    extern __shared__ __align__(16) char smem[];
    uint32_t sb = smem_u32(smem);
    int tid = threadIdx.x;

    int arow = tid >> 3;
    int acol = (tid & 7) * 8;
    const __half* asrc[4];
#pragma unroll
    for (int i = 0; i < 4; i++) {
        int lr = mt0 + arow + i * 32; if (lr >= cnt) lr = mt0;
        asrc[i] = g_h + (size_t)(hbase + lr) * HID + acol;
    }
    uint32_t adst = (uint32_t)(arow * RSB + (tid & 7) * 16);
    const __half* bsrc[4];
#pragma unroll
    for (int i = 0; i < 4; i++)
        bsrc[i] = pd + (size_t)(n0 + arow + i * 32) * HID + acol;
    uint32_t bdst = adst;

    const int NKT = HID / BKH;  // 64
    auto issue = [&](int s, int kt) {
        uint32_t st = sb + (uint32_t)s * DN_ST;
        size_t kh = (size_t)kt * BKH;
#pragma unroll
        for (int i = 0; i < 4; i++) cp16(st + adst + i * 32 * RSB, asrc[i] + kh);
#pragma unroll
        for (int i = 0; i < 4; i++) cp16(st + DN_B_OFF + bdst + i * 32 * RSB, bsrc[i] + kh);
    };

    issue(0, 0); CP_COMMIT();
    issue(1, 1); CP_COMMIT();

    int warp = tid >> 5, lane = tid & 31;
    int wm = (warp & 3) * 32;
    int wng = warp >> 2;
    int gid = lane >> 2, tig = lane & 3;
    int lg = lane >> 3, l8 = lane & 7;
    uint32_t a_ls = (uint32_t)((wm + (lg & 1) * 8 + l8) * RSB + (lg >> 1) * 16);
    uint32_t b_ls = (uint32_t)((wng * 64 + (lg & 1) * 8 + l8) * RSB + (lg >> 1) * 16);

    float acc[2][8][4];
#pragma unroll
    for (int a = 0; a < 2; a++)
#pragma unroll
        for (int b = 0; b < 8; b++)
#pragma unroll
            for (int c = 0; c < 4; c++) acc[a][b][c] = 0.f;

    int slot = 0;
    for (int kt = 0; kt < NKT; kt++) {
        CP_WAIT1();
        __syncthreads();
        if (kt + 2 < NKT) {
            int s2 = slot + 2; if (s2 >= STAGES) s2 -= STAGES;
            issue(s2, kt + 2); CP_COMMIT();
        }
        uint32_t stg = sb + (uint32_t)slot * DN_ST;
#pragma unroll
        for (int ks = 0; ks < 4; ks++) {
            uint32_t ko = ks * 32;
            unsigned af[2][4];
            ldsm4(af[0], stg + a_ls + ko);
            ldsm4(af[1], stg + a_ls + 16 * RSB + ko);
#pragma unroll
            for (int j = 0; j < 4; j++) {
                unsigned bb[4];
                ldsm4(bb, stg + DN_B_OFF + b_ls + j * 16 * RSB + ko);
                unsigned be[2] = { bb[0], bb[2] }, bo[2] = { bb[1], bb[3] };
#pragma unroll
                for (int mt = 0; mt < 2; mt++) {
                    mma_f16(acc[mt][j * 2],     af[mt], be);
                    mma_f16(acc[mt][j * 2 + 1], af[mt], bo);
                }
            }
        }
        if (++slot == STAGES) slot = 0;
    }

    // epilogue: y[dst] = wt * acc
    int wn = wng * 64;
#pragma unroll
    for (int mt = 0; mt < 2; mt++) {
#pragma unroll
        for (int rr = 0; rr < 2; rr++) {
            int row = wm + mt * 16 + gid + rr * 8;
            int lr = mt0 + row;
            if (lr >= cnt) continue;
            int dst; float wt;
            if (grp < NE) { int q = grp * NTOK + lr; dst = g_dst[q]; wt = g_wt[q]; }
            else          { dst = lr * 3 + 2;        wt = 1.f; }
            float* yp = g_y + (size_t)dst * DM + n0 + wn + tig * 2;
#pragma unroll
            for (int nt = 0; nt < 8; nt++) {
                float2 o;
                o.x = wt * acc[mt][nt][rr * 2];
                o.y = wt * acc[mt][nt][rr * 2 + 1];
                *(float2*)(yp + nt * 8) = o;
            }
        }
    }
}

// ---------------- combine ----------------
__global__ void combine_kernel(float* __restrict__ out) {
    int i = blockIdx.x * blockDim.x + threadIdx.x;
    if (i >= NTOK * DM) return;
    int n = i / DM, c = i % DM;
    size_t b = (size_t)n * 3 * DM + c;
    out[i] = g_y[b] + g_y[b + DM] + g_y[b + 2 * DM];
}

// ---------------- launch ----------------
extern "C" void kernel_launch(void* const* d_in, const int* in_sizes, int n_in,
                              void* d_out, int out_size) {
    const float* x   = (const float*)d_in[0];
    const float* rw  = (const float*)d_in[1];
    const float* wg  = (const float*)d_in[2];
    const float* wu  = (const float*)d_in[3];
    const float* wd  = (const float*)d_in[4];
    const float* swg = (const float*)d_in[5];
    const float* swu = (const float*)d_in[6];
    const float* swd = (const float*)d_in[7];
    float* out = (float*)d_out;

    const int UP_SMEM = STAGES * UP_ST;   // 110592
    const int DN_SMEM = STAGES * DN_ST;   // 110592
    cudaFuncSetAttribute(up_kernel,   cudaFuncAttributeMaxDynamicSharedMemorySize, UP_SMEM);
    cudaFuncSetAttribute(down_kernel, cudaFuncAttributeMaxDynamicSharedMemorySize, DN_SMEM);

    dim3 gw(DM / 64, HID / 64, NE);
    cvt_wT_kernel<<<gw, 256>>>(wg, 0, DM, HID);
    cvt_wT_kernel<<<gw, 256>>>(wu, 1, DM, HID);
    dim3 gwd(HID / 64, DM / 64, NE);
    cvt_wT_kernel<<<gwd, 256>>>(wd, 2, HID, DM);
    dim3 gs(DM / 64, HID / 64, 1);
    cvt_wT_kernel<<<gs, 256>>>(swg, 3, DM, HID);
    cvt_wT_kernel<<<gs, 256>>>(swu, 4, DM, HID);
    dim3 gsd(HID / 64, DM / 64, 1);
    cvt_wT_kernel<<<gsd, 256>>>(swd, 5, HID, DM);
    const int X8 = NTOK * DM / 8;
    cvt_x_kernel<<<(X8 + 255) / 256, 256>>>((const float4*)x, X8);

    zero_kernel<<<1, 32>>>();
    router_kernel<<<NTOK / 8, 256>>>(x, rw);
    scan_kernel<<<1, 32>>>();

    dim3 gu(NTOK / BM, HID / 64, 8);    // (64, 64, 8)
    up_kernel<<<gu, 256, UP_SMEM>>>();

    dim3 gd(NTOK / BM, DM / 128, 8);    // (64, 8, 8)
    down_kernel<<<gd, 256, DN_SMEM>>>();

    combine_kernel<<<(NTOK * DM) / 256, 256>>>(out);
}